// round 1
// baseline (speedup 1.0000x reference)
#include <cuda_runtime.h>

// BilateralBlur: fused horizontal+vertical depth-guided 5-tap blur + contrast blend.
// Shapes fixed by the problem: B=8, H=1024, W=1024, C=1, R=2 (K=5).

#define BATCH 8
#define HDIM 1024
#define WDIM 1024
#define TW 32
#define TH 32
#define HALO 2
#define TWH (TW + 2*HALO)   // 36
#define THH (TH + 2*HALO)   // 36
#define PITCH (TWH + 1)     // 37 (conflict-free)
#define XPITCH (TW + 1)     // 33

__global__ __launch_bounds__(256, 4)
void bilat_fused_kernel(const float* __restrict__ bright,
                        const float* __restrict__ dark,
                        const float* __restrict__ depths,
                        const float* __restrict__ s_dv,
                        const float* __restrict__ s_sv,
                        const float* __restrict__ s_de,
                        const float* __restrict__ s_eps,
                        const float* __restrict__ s_ce,
                        float* __restrict__ out)
{
    __shared__ float sb[THH * PITCH];
    __shared__ float sd[THH * PITCH];
    __shared__ float sz[THH * PITCH];
    __shared__ float sbx[THH * XPITCH];
    __shared__ float sdx[THH * XPITCH];

    const float dv  = __ldg(s_dv);
    const float sv  = __ldg(s_sv);
    const float de  = __ldg(s_de);
    const float eps = __ldg(s_eps);
    const float ce  = __ldg(s_ce);
    const float inv2dv = 0.5f / dv;
    const float inv2sv = 0.5f / sv;

    float sw[5];
    #pragma unroll
    for (int i = 0; i < 5; i++) {
        float t = (float)(i - 2);
        sw[i] = __expf(-t * t * inv2sv);
    }

    const int bx0 = blockIdx.x * TW;
    const int by0 = blockIdx.y * TH;
    const int batch = blockIdx.z;
    const long base = (long)batch * HDIM * WDIM;
    const int tid = threadIdx.x;  // 0..255

    // ---- Phase 1: load (THH x TWH) halo tile of bright/dark/depths (zero pad OOB)
    for (int i = tid; i < THH * TWH; i += 256) {
        int r = i / TWH, c = i % TWH;
        int gy = by0 + r - HALO;
        int gx = bx0 + c - HALO;
        float b = 0.f, d = 0.f, z = 0.f;
        if (gy >= 0 && gy < HDIM && gx >= 0 && gx < WDIM) {
            long g = base + (long)gy * WDIM + gx;
            b = __ldg(bright + g);
            d = __ldg(dark + g);
            z = __ldg(depths + g);
        }
        sb[r * PITCH + c] = b;
        sd[r * PITCH + c] = d;
        sz[r * PITCH + c] = z;
    }
    __syncthreads();

    // ---- Phase 2: horizontal blur for all THH rows (incl. row halo), TW output cols.
    // Rows outside the image produce bx=dx=0 (matches reference's zero-padding of
    // bright_x/dark_x before the vertical pass; avoids NaN from 1/0 depth).
    for (int i = tid; i < THH * TW; i += 256) {
        int r = i / TW, c = i % TW;
        int gy = by0 + r - HALO;
        float bxv = 0.f, dxv = 0.f;
        if (gy >= 0 && gy < HDIM) {
            const float* zr = &sz[r * PITCH];
            const float* br = &sb[r * PITCH];
            const float* dr = &sd[r * PITCH];
            float zc = zr[c + HALO];
            float invz = 1.0f / zc;      // center depth is a valid pixel (>0)
            float wsum = 0.f, bs = 0.f, ds = 0.f;
            #pragma unroll
            for (int k = 0; k < 5; k++) {
                float zp = zr[c + k];
                float rel = fminf(fabsf(fmaf(zp, invz, -1.0f)), 1.0f);
                float w = sw[k] * __expf(-rel * rel * inv2dv);
                wsum += w;
                bs = fmaf(w, br[c + k], bs);
                ds = fmaf(w, dr[c + k], ds);
            }
            float inw = 1.0f / wsum;     // wsum >= 1 (center tap weight = 1)
            bxv = bs * inw;
            dxv = ds * inw;
        }
        sbx[r * XPITCH + c] = bxv;
        sdx[r * XPITCH + c] = dxv;
    }
    __syncthreads();

    // ---- Phase 3: vertical blur on (bx,dx) + contrast-aware blend, write out.
    for (int i = tid; i < TH * TW; i += 256) {
        int r = i / TW, c = i % TW;
        int gy = by0 + r, gx = bx0 + c;

        float zc = sz[(r + HALO) * PITCH + c + HALO];
        float invz = 1.0f / zc;
        float wsum = 0.f, bs = 0.f, ds = 0.f;
        #pragma unroll
        for (int k = 0; k < 5; k++) {
            float zp = sz[(r + k) * PITCH + c + HALO];
            float rel = fminf(fabsf(fmaf(zp, invz, -1.0f)), 1.0f);
            float w = sw[k] * __expf(-rel * rel * inv2dv);
            wsum += w;
            bs = fmaf(w, sbx[(r + k) * XPITCH + c], bs);
            ds = fmaf(w, sdx[(r + k) * XPITCH + c], ds);
        }
        float inw = 1.0f / wsum;
        float bm = bs * inw;
        float dm = ds * inw;

        float b = sb[(r + HALO) * PITCH + c + HALO];
        float d = sd[(r + HALO) * PITCH + c + HALO];

        // _custom_pow(a, de) = exp(de * log(max(a, 1e-8)))
        float devb = __expf(de * __logf(fmaxf(fabsf(b - bm), 1e-8f))) * ce;
        float devd = fmaxf(__expf(de * __logf(fmaxf(fabsf(d - dm), 1e-8f))), eps);
        float s = 1.0f / (devb + devd);

        out[base + (long)gy * WDIM + gx] = (devd * b + devb * d) * s;
    }
}

extern "C" void kernel_launch(void* const* d_in, const int* in_sizes, int n_in,
                              void* d_out, int out_size)
{
    const float* bright = (const float*)d_in[0];
    const float* dark   = (const float*)d_in[1];
    const float* depths = (const float*)d_in[2];
    const float* dv     = (const float*)d_in[3];
    const float* sv     = (const float*)d_in[4];
    const float* de     = (const float*)d_in[5];
    const float* eps    = (const float*)d_in[6];
    const float* ce     = (const float*)d_in[7];
    float* out = (float*)d_out;

    dim3 grid(WDIM / TW, HDIM / TH, BATCH);
    bilat_fused_kernel<<<grid, 256>>>(bright, dark, depths, dv, sv, de, eps, ce, out);
}

// round 2
// speedup vs baseline: 1.4270x; 1.4270x over previous
#include <cuda_runtime.h>

// BilateralBlur: streaming fused separable depth-guided blur + contrast blend.
// B=8, H=1024, W=1024, R=2 (K=5 taps).
// Block = 128 threads = 128 columns; strip of 64 output rows per block.
// Rows stream through a 5-deep register ring (chunk=5 => static ring slots).

#define HDIM 1024
#define WDIM 1024
#define BATCH 8
#define TW 128
#define HSTRIP 64
#define CHUNK 5
#define SPITCH 132          // 128 + 4 halo
#define NROWS 68            // HSTRIP + 4
#define NCHUNK 14           // ceil(68/5) = 14 (covers m=0..69, m>=68 masked)

__device__ __forceinline__ float f_ex2(float x){ float y; asm("ex2.approx.ftz.f32 %0, %1;" : "=f"(y) : "f"(x)); return y; }
__device__ __forceinline__ float f_lg2(float x){ float y; asm("lg2.approx.ftz.f32 %0, %1;" : "=f"(y) : "f"(x)); return y; }
__device__ __forceinline__ float f_rcp(float x){ float y; asm("rcp.approx.ftz.f32 %0, %1;" : "=f"(y) : "f"(x)); return y; }

__global__ __launch_bounds__(128)
void bilat_stream_kernel(const float* __restrict__ bright,
                         const float* __restrict__ dark,
                         const float* __restrict__ depths,
                         const float* __restrict__ s_dv,
                         const float* __restrict__ s_sv,
                         const float* __restrict__ s_de,
                         const float* __restrict__ s_eps,
                         const float* __restrict__ s_ce,
                         float* __restrict__ out)
{
    __shared__ float sB[CHUNK][SPITCH];
    __shared__ float sD[CHUNK][SPITCH];
    __shared__ float sZ[CHUNK][SPITCH];

    const float L2E = 1.4426950408889634f;
    const float dv  = __ldg(s_dv);
    const float sv  = __ldg(s_sv);
    const float de  = __ldg(s_de);
    const float eps = __ldg(s_eps);
    const float ce  = __ldg(s_ce);
    const float c1  = -L2E / (2.0f * dv);      // exponent coeff for rel^2
    const float q   = -L2E / (2.0f * sv);      // spatial term in log2 space
    float swl[5];
    #pragma unroll
    for (int k = 0; k < 5; k++) { float t = (float)(k - 2); swl[k] = t * t * q; }

    const int tid   = threadIdx.x;                 // 0..127 = column in tile
    const int x0    = blockIdx.x * TW;
    const int y0    = blockIdx.y * HSTRIP;
    const int base  = blockIdx.z * (HDIM * WDIM);
    const int gxc   = x0 + tid;                    // output column (always valid)
    const int gx1   = x0 - 2 + tid;                // halo-load column 1
    const int gx2   = x0 + 126 + tid;              // halo-load column 2 (tid<4)
    const bool v1   = (gx1 >= 0) & (gx1 < WDIM);
    const bool v2   = (gx2 < WDIM);                // gx2 >= 126 always >= 0

    // register rings (stream row m -> slot m%5; chunk=5 keeps slots static)
    float rz[5], riz[5], rbx[5], rdx[5], rbc[5], rdc[5];

    for (int c = 0; c < NCHUNK; c++) {
        // ---- load CHUNK rows of raw b/d/z with x-halo into shared
        #pragma unroll
        for (int rr = 0; rr < CHUNK; rr++) {
            const int m  = c * CHUNK + rr;
            const int gy = y0 - 2 + m;
            const bool rv = (gy >= 0) & (gy < HDIM) & (m < NROWS);
            float b = 0.f, d = 0.f, z = 0.f;
            if (rv & v1) {
                int g = base + gy * WDIM + gx1;
                b = __ldg(bright + g); d = __ldg(dark + g); z = __ldg(depths + g);
            }
            sB[rr][tid] = b; sD[rr][tid] = d; sZ[rr][tid] = z;
            if (tid < 4) {
                float b2 = 0.f, d2 = 0.f, z2 = 0.f;
                if (rv & v2) {
                    int g = base + gy * WDIM + gx2;
                    b2 = __ldg(bright + g); d2 = __ldg(dark + g); z2 = __ldg(depths + g);
                }
                sB[rr][128 + tid] = b2; sD[rr][128 + tid] = d2; sZ[rr][128 + tid] = z2;
            }
        }
        __syncthreads();

        // ---- horizontal blur per row -> push ring; emit output row m-4 offset
        #pragma unroll
        for (int rr = 0; rr < CHUNK; rr++) {
            const int m  = c * CHUNK + rr;
            const int gy = y0 - 2 + m;
            float bx = 0.f, dx = 0.f, zc = 0.f, iz = 0.f, bc = 0.f, dc = 0.f;
            if ((gy >= 0) & (gy < HDIM) & (m < NROWS)) {
                zc = sZ[rr][tid + 2];
                bc = sB[rr][tid + 2];
                dc = sD[rr][tid + 2];
                iz = f_rcp(zc);
                float ws = 0.f, bs = 0.f, ds = 0.f;
                #pragma unroll
                for (int k = 0; k < 5; k++) {
                    float zp = (k == 2) ? zc : sZ[rr][tid + k];
                    float bp = (k == 2) ? bc : sB[rr][tid + k];
                    float dp = (k == 2) ? dc : sD[rr][tid + k];
                    float rel = fminf(fabsf(fmaf(zp, iz, -1.0f)), 1.0f);
                    float w = f_ex2(fmaf(rel * rel, c1, swl[k]));
                    ws += w;
                    bs = fmaf(w, bp, bs);
                    ds = fmaf(w, dp, ds);
                }
                float r = f_rcp(ws);
                bx = bs * r; dx = ds * r;
            }
            rz[rr] = zc; riz[rr] = iz; rbx[rr] = bx; rdx[rr] = dx;
            rbc[rr] = bc; rdc[rr] = dc;

            // output stream row (m-2), i.e. image row y0 + m - 4
            if (m >= 4 && (m - 4) < HSTRIP) {
                const int sc = (rr + 3) % 5;          // center slot: (m-2)%5
                const float izc = riz[sc];
                float ws = 0.f, bs = 0.f, ds = 0.f;
                #pragma unroll
                for (int j = 0; j < 5; j++) {
                    const int sj = (rr + 1 + j) % 5;  // tap row m-4+j
                    float rel = fminf(fabsf(fmaf(rz[sj], izc, -1.0f)), 1.0f);
                    float w = f_ex2(fmaf(rel * rel, c1, swl[j]));
                    ws += w;
                    bs = fmaf(w, rbx[sj], bs);
                    ds = fmaf(w, rdx[sj], ds);
                }
                float r  = f_rcp(ws);
                float bm = bs * r, dm = ds * r;
                float b  = rbc[sc], d = rdc[sc];

                // custom_pow(a, de) = exp2(de * log2(max(a,1e-8)))
                float devb = f_ex2(de * f_lg2(fmaxf(fabsf(b - bm), 1e-8f))) * ce;
                float devd = fmaxf(f_ex2(de * f_lg2(fmaxf(fabsf(d - dm), 1e-8f))), eps);
                float s = f_rcp(devb + devd);
                out[base + (y0 + m - 4) * WDIM + gxc] = (devd * b + devb * d) * s;
            }
        }
        __syncthreads();
    }
}

extern "C" void kernel_launch(void* const* d_in, const int* in_sizes, int n_in,
                              void* d_out, int out_size)
{
    const float* bright = (const float*)d_in[0];
    const float* dark   = (const float*)d_in[1];
    const float* depths = (const float*)d_in[2];
    const float* dv     = (const float*)d_in[3];
    const float* sv     = (const float*)d_in[4];
    const float* de     = (const float*)d_in[5];
    const float* eps    = (const float*)d_in[6];
    const float* ce     = (const float*)d_in[7];
    float* out = (float*)d_out;

    dim3 grid(WDIM / TW, HDIM / HSTRIP, BATCH);
    bilat_stream_kernel<<<grid, TW>>>(bright, dark, depths, dv, sv, de, eps, ce, out);
}